// round 2
// baseline (speedup 1.0000x reference)
#include <cuda_runtime.h>
#include <cuda_bf16.h>
#include <cstdint>

#define SLEN   1024
#define BSZ    32
#define HID    1024
#define INDIM  1024
#define M_TOTAL (SLEN * BSZ)   // 32768

// Scratch for the pre-activation projections (allocation-free rule: __device__ globals)
__device__ float g_z[(size_t)M_TOTAL * HID];   // 128 MB
__device__ float g_f[(size_t)M_TOTAL * HID];   // 128 MB

// ---------------------------------------------------------------------------
// GEMM: C_z[m][n] = sum_k x[m][k] * wm_z[n][k]   (and same for f, shared x tile)
// x:   [M_TOTAL, INDIM] row-major (m = s*BSZ + b)
// wm:  [HID, INDIM] row-major
// ---------------------------------------------------------------------------
#define BM 128
#define BN 64
#define BK 16

__global__ __launch_bounds__(256, 2)
void gemm_zf_kernel(const float* __restrict__ x,
                    const float* __restrict__ wz,
                    const float* __restrict__ wf) {
    __shared__ float xs[BM][BK + 1];        // [row][k], pad 1 -> stride 17
    __shared__ float wzs[BK][BN + 4];       // [k][n],  pad 4 -> stride 68 (keeps 16B align)
    __shared__ float wfs[BK][BN + 4];

    const int tid = threadIdx.x;
    const int m0 = blockIdx.y * BM;
    const int n0 = blockIdx.x * BN;
    const int tx = tid & 15;    // n: 4 cols each -> 64
    const int ty = tid >> 4;    // m: 8 rows each -> 128

    float accz[8][4];
    float accf[8][4];
#pragma unroll
    for (int i = 0; i < 8; i++)
#pragma unroll
        for (int j = 0; j < 4; j++) { accz[i][j] = 0.f; accf[i][j] = 0.f; }

    // w-tile load mapping (reused each k-tile)
    const int wrow = tid >> 2;         // n index 0..63
    const int wkc  = (tid & 3) * 4;    // k offset 0,4,8,12

    for (int k0 = 0; k0 < INDIM; k0 += BK) {
        // load x tile: 128 rows x 16 k = 512 float4, 2 per thread
#pragma unroll
        for (int l = 0; l < 2; l++) {
            int slot = tid + l * 256;
            int row  = slot >> 2;
            int kc   = (slot & 3) * 4;
            float4 v = *(const float4*)(x + (size_t)(m0 + row) * INDIM + k0 + kc);
            xs[row][kc + 0] = v.x; xs[row][kc + 1] = v.y;
            xs[row][kc + 2] = v.z; xs[row][kc + 3] = v.w;
        }
        // load w tiles transposed to [k][n]
        {
            float4 vz = *(const float4*)(wz + (size_t)(n0 + wrow) * INDIM + k0 + wkc);
            float4 vf = *(const float4*)(wf + (size_t)(n0 + wrow) * INDIM + k0 + wkc);
            wzs[wkc + 0][wrow] = vz.x; wzs[wkc + 1][wrow] = vz.y;
            wzs[wkc + 2][wrow] = vz.z; wzs[wkc + 3][wrow] = vz.w;
            wfs[wkc + 0][wrow] = vf.x; wfs[wkc + 1][wrow] = vf.y;
            wfs[wkc + 2][wrow] = vf.z; wfs[wkc + 3][wrow] = vf.w;
        }
        __syncthreads();

#pragma unroll
        for (int k = 0; k < BK; k++) {
            float a[8];
#pragma unroll
            for (int i = 0; i < 8; i++) a[i] = xs[ty * 8 + i][k];
            const float4 bz = *(const float4*)(&wzs[k][tx * 4]);
            const float4 bf = *(const float4*)(&wfs[k][tx * 4]);
#pragma unroll
            for (int i = 0; i < 8; i++) {
                accz[i][0] += a[i] * bz.x;
                accz[i][1] += a[i] * bz.y;
                accz[i][2] += a[i] * bz.z;
                accz[i][3] += a[i] * bz.w;
                accf[i][0] += a[i] * bf.x;
                accf[i][1] += a[i] * bf.y;
                accf[i][2] += a[i] * bf.z;
                accf[i][3] += a[i] * bf.w;
            }
        }
        __syncthreads();
    }

    // epilogue: coalesced float4 stores
#pragma unroll
    for (int i = 0; i < 8; i++) {
        size_t row = (size_t)(m0 + ty * 8 + i);
        size_t off = row * HID + n0 + tx * 4;
        float4 vz = make_float4(accz[i][0], accz[i][1], accz[i][2], accz[i][3]);
        float4 vf = make_float4(accf[i][0], accf[i][1], accf[i][2], accf[i][3]);
        *(float4*)(g_z + off) = vz;
        *(float4*)(g_f + off) = vf;
    }
}

// ---------------------------------------------------------------------------
// Sequential scan over slen, one thread per (b,h) channel.
// ---------------------------------------------------------------------------
__device__ __forceinline__ float tanh_fast(float v) {
    float r;
    asm("tanh.approx.f32 %0, %1;" : "=f"(r) : "f"(v));
    return r;
}
__device__ __forceinline__ float sigmoid_fast(float v) {
    return 0.5f * tanh_fast(0.5f * v) + 0.5f;
}

__device__ __forceinline__ float lstm_step(float cell, float z, float f,
                                           float wz, float wf, float bz, float bf) {
    float zp = tanh_fast(fmaf(wz, cell, z + bz));
    float fp = sigmoid_fast(fmaf(wf, cell, f + bf));
    return cell * fp + (1.0f - fp) * zp;
}

__global__ __launch_bounds__(256)
void scan_kernel(const float* __restrict__ state,
                 const float* __restrict__ wvz, const float* __restrict__ wvf,
                 const float* __restrict__ bz_, const float* __restrict__ bf_,
                 float* __restrict__ out) {
    const int c = blockIdx.x * blockDim.x + threadIdx.x;   // 0..32767
    const int h = c & (HID - 1);

    float cell = state[c];
    const float wz  = wvz[h];
    const float wf  = wvf[h];
    const float bzv = bz_[h];
    const float bfv = bf_[h];

    const float* zp = g_z + c;
    const float* fp = g_f + c;
    float*       op = out + c;

#pragma unroll 1
    for (int s = 0; s < SLEN; s += 4) {
        size_t i0 = (size_t)s * M_TOTAL;
        // issue 8 independent loads up front (MLP)
        float z0 = zp[i0];
        float z1 = zp[i0 + (size_t)M_TOTAL];
        float z2 = zp[i0 + (size_t)2 * M_TOTAL];
        float z3 = zp[i0 + (size_t)3 * M_TOTAL];
        float f0 = fp[i0];
        float f1 = fp[i0 + (size_t)M_TOTAL];
        float f2 = fp[i0 + (size_t)2 * M_TOTAL];
        float f3 = fp[i0 + (size_t)3 * M_TOTAL];

        cell = lstm_step(cell, z0, f0, wz, wf, bzv, bfv);
        op[i0] = cell;
        cell = lstm_step(cell, z1, f1, wz, wf, bzv, bfv);
        op[i0 + (size_t)M_TOTAL] = cell;
        cell = lstm_step(cell, z2, f2, wz, wf, bzv, bfv);
        op[i0 + (size_t)2 * M_TOTAL] = cell;
        cell = lstm_step(cell, z3, f3, wz, wf, bzv, bfv);
        op[i0 + (size_t)3 * M_TOTAL] = cell;
    }
}

// ---------------------------------------------------------------------------
extern "C" void kernel_launch(void* const* d_in, const int* in_sizes, int n_in,
                              void* d_out, int out_size) {
    const float* x      = (const float*)d_in[0];
    const float* state  = (const float*)d_in[1];
    const float* wm_z   = (const float*)d_in[2];
    const float* wm_f   = (const float*)d_in[3];
    const float* wv_z   = (const float*)d_in[4];
    const float* wv_f   = (const float*)d_in[5];
    const float* bias_z = (const float*)d_in[6];
    const float* bias_f = (const float*)d_in[7];
    float* out = (float*)d_out;

    dim3 grid(HID / BN, M_TOTAL / BM);   // (16, 256)
    gemm_zf_kernel<<<grid, 256>>>(x, wm_z, wm_f);
    scan_kernel<<<M_TOTAL / 256, 256>>>(state, wv_z, wv_f, bias_z, bias_f, out);
}

// round 5
// speedup vs baseline: 3.7462x; 3.7462x over previous
#include <cuda_runtime.h>
#include <cstdint>

#define SLEN   1024
#define BSZ    32
#define HID    1024
#define INDIM  1024
#define M_TOTAL (SLEN * BSZ)   // 32768
#define NFUSED  (2 * HID)      // z and f stacked: 2048

// -------- scratch (__device__ globals: allocation-free rule) --------
__device__ float g_z [(size_t)M_TOTAL * HID];      // z pre-act + bias_z
__device__ float g_f [(size_t)M_TOTAL * HID];      // 0.5*(f pre-act + bias_f)
__device__ float g_af[(size_t)M_TOTAL * INDIM];    // x in mma-fragment order (tf32-rna)
__device__ float g_bf[(size_t)NFUSED * INDIM];     // fused weights in fragment order

__device__ __forceinline__ float rna(float v) {
    uint32_t r;
    asm("cvt.rna.tf32.f32 %0, %1;" : "=r"(r) : "f"(v));
    return __uint_as_float(r);
}

// ============ pre-pass: x -> A-fragment order ============
// A-frag unit u (16B): lane=u&31, kt=(u>>5)&127, mt=u>>12
// regs: a0=(m,k) a1=(m+8,k) a2=(m,k+4) a3=(m+8,k+4), m=mt*16+g, k=kt*8+tg
__global__ __launch_bounds__(256)
void prep_a(const float* __restrict__ x, float* __restrict__ Af) {
    size_t u = (size_t)blockIdx.x * 256 + threadIdx.x;      // 0 .. 8388607
    int lane = (int)(u & 31);
    size_t t2 = u >> 5;
    int kt = (int)(t2 & 127);
    int mt = (int)(t2 >> 7);
    int g = lane >> 2, tg = lane & 3;
    size_t m = (size_t)mt * 16 + g;
    int    k = kt * 8 + tg;
    float4 v;
    v.x = rna(x[m * INDIM + k]);
    v.y = rna(x[(m + 8) * INDIM + k]);
    v.z = rna(x[m * INDIM + k + 4]);
    v.w = rna(x[(m + 8) * INDIM + k + 4]);
    ((float4*)Af)[u] = v;
}

// ============ pre-pass: weights -> B-fragment order (fused z|f) ============
// unit u (8B): lane=u&31, kt=(u>>5)&127, nt=u>>12 ; b0=(k,n) b1=(k+4,n), n=nt*8+g, k=kt*8+tg
__global__ __launch_bounds__(256)
void prep_b(const float* __restrict__ wz, const float* __restrict__ wf,
            float* __restrict__ Bf) {
    size_t u = (size_t)blockIdx.x * 256 + threadIdx.x;      // 0 .. 1048575
    int lane = (int)(u & 31);
    size_t t2 = u >> 5;
    int kt = (int)(t2 & 127);
    int nt = (int)(t2 >> 7);
    int n = nt * 8 + (lane >> 2);
    int k = kt * 8 + (lane & 3);
    const float* w = (n < HID) ? (wz + (size_t)n * INDIM)
                               : (wf + (size_t)(n - HID) * INDIM);
    float2 v;
    v.x = rna(w[k]);
    v.y = rna(w[k + 4]);
    ((float2*)Bf)[u] = v;
}

// ============ tf32 mma.sync GEMM ============
// CTA: 256 thr (8 warps, 2x4), tile 128(M) x 256(fused N), KC=32, 3-stage cp.async
#define BM 128
#define BN 256
#define KC 32
#define NCH (INDIM / KC)          // 32
#define STAGE_BYTES 49152         // A 16KB + B 32KB
#define SMEM_BYTES  (3 * STAGE_BYTES)

__device__ __forceinline__ void cp16(uint32_t dst, const void* src) {
    asm volatile("cp.async.cg.shared.global [%0], [%1], 16;" :: "r"(dst), "l"(src));
}

__device__ __forceinline__ void mma8(float* d, const uint32_t* a, const uint32_t* b) {
    asm volatile(
        "mma.sync.aligned.m16n8k8.row.col.f32.tf32.tf32.f32 "
        "{%0,%1,%2,%3}, {%4,%5,%6,%7}, {%8,%9}, {%0,%1,%2,%3};"
        : "+f"(d[0]), "+f"(d[1]), "+f"(d[2]), "+f"(d[3])
        : "r"(a[0]), "r"(a[1]), "r"(a[2]), "r"(a[3]), "r"(b[0]), "r"(b[1]));
}

__global__ __launch_bounds__(256, 1)
void gemm_tc(const float* __restrict__ Af, const float* __restrict__ Bf,
             const float* __restrict__ bz, const float* __restrict__ bfb) {
    extern __shared__ char smemc[];
    const int tid  = threadIdx.x;
    const int lane = tid & 31;
    const int wid  = tid >> 5;
    const int wm   = wid >> 2;     // 0..1 : 64 M-rows each
    const int wn   = wid & 3;      // 0..3 : 64 N-cols each
    const int mt0  = blockIdx.y * (BM / 16);   // 8 m16-tiles per CTA
    const int nt0  = blockIdx.x * (BN / 8);    // 32 n8-tiles per CTA

    float d[4][8][4];
#pragma unroll
    for (int i = 0; i < 4; i++)
#pragma unroll
        for (int j = 0; j < 8; j++)
#pragma unroll
            for (int q = 0; q < 4; q++) d[i][j][q] = 0.f;

    auto load_chunk = [&](int st, int c) {
        char* stA = smemc + st * STAGE_BYTES;
        char* stB = stA + 16384;
        const int kt0 = c * 4;
#pragma unroll
        for (int t = 0; t < 4; t++) {                // A: 1024 x 16B
            int idx = tid + t * 256;
            int l = idx & 31, slot = idx >> 5;       // slot = mtl*4 + kt
            const float* src = Af +
                ((((size_t)(mt0 + (slot >> 2)) * 128) + (kt0 + (slot & 3))) * 32 + l) * 4;
            cp16((uint32_t)__cvta_generic_to_shared(stA + idx * 16), src);
        }
#pragma unroll
        for (int t = 0; t < 8; t++) {                // B: 2048 x 16B
            int idx = tid + t * 256;
            int pair = idx & 15, slot = idx >> 4;    // slot = ntl*4 + kt
            const float* src = Bf +
                ((((size_t)(nt0 + (slot >> 2)) * 128) + (kt0 + (slot & 3))) * 32 + pair * 2) * 2;
            cp16((uint32_t)__cvta_generic_to_shared(stB + idx * 16), src);
        }
        asm volatile("cp.async.commit_group;" ::: "memory");
    };

    load_chunk(0, 0);
    load_chunk(1, 1);

    for (int c = 0; c < NCH; ++c) {
        if (c + 1 < NCH) asm volatile("cp.async.wait_group 1;" ::: "memory");
        else             asm volatile("cp.async.wait_group 0;" ::: "memory");
        __syncthreads();

        const int st = c % 3;
        const float* stA = (const float*)(smemc + st * STAGE_BYTES);
        const float* stB = stA + 4096;
#pragma unroll
        for (int kt = 0; kt < 4; kt++) {
            uint32_t a[4][4], b[8][2];
#pragma unroll
            for (int i = 0; i < 4; i++) {
                float4 v = *(const float4*)(stA + (((wm * 4 + i) * 4 + kt) * 32 + lane) * 4);
                a[i][0] = __float_as_uint(v.x); a[i][1] = __float_as_uint(v.y);
                a[i][2] = __float_as_uint(v.z); a[i][3] = __float_as_uint(v.w);
            }
#pragma unroll
            for (int j = 0; j < 8; j++) {
                float2 v = *(const float2*)(stB + (((wn * 8 + j) * 4 + kt) * 32 + lane) * 2);
                b[j][0] = __float_as_uint(v.x); b[j][1] = __float_as_uint(v.y);
            }
#pragma unroll
            for (int i = 0; i < 4; i++)
#pragma unroll
                for (int j = 0; j < 8; j++) mma8(d[i][j], a[i], b[j]);
        }

        if (c + 2 < NCH) load_chunk((c + 2) % 3, c + 2);
    }

    // ---- epilogue: +bias, 0.5x for f-half, store to g_z / g_f ----
    const int g  = lane >> 2, tg = lane & 3;
    const int n0f = nt0 * 8;                     // fused col base (multiple of 256)
    const bool isF = (n0f >= HID);
    float*       outp  = isF ? g_f : g_z;
    const float* bp    = isF ? bfb : bz;
    const float  scale = isF ? 0.5f : 1.0f;
    const int colBase  = (n0f - (isF ? HID : 0)) + wn * 64;

#pragma unroll
    for (int j = 0; j < 8; j++) {
        const int col = colBase + j * 8 + 2 * tg;
        const float2 bb = *(const float2*)(bp + col);
#pragma unroll
        for (int i = 0; i < 4; i++) {
            const size_t row = (size_t)blockIdx.y * BM + wm * 64 + i * 16 + g;
            float2 v0, v1;
            v0.x = scale * (d[i][j][0] + bb.x);
            v0.y = scale * (d[i][j][1] + bb.y);
            v1.x = scale * (d[i][j][2] + bb.x);
            v1.y = scale * (d[i][j][3] + bb.y);
            *(float2*)(outp + row * HID + col)       = v0;
            *(float2*)(outp + (row + 8) * HID + col) = v1;
        }
    }
}

// ============ sequential scan ============
__device__ __forceinline__ float tanh_fast(float v) {
    float r;
    asm("tanh.approx.f32 %0, %1;" : "=f"(r) : "f"(v));
    return r;
}

__global__ __launch_bounds__(128)
void scan_kernel(const float* __restrict__ state,
                 const float* __restrict__ wvz, const float* __restrict__ wvf,
                 float* __restrict__ out) {
    const int c = blockIdx.x * blockDim.x + threadIdx.x;   // (b,h) channel
    const int h = c & (HID - 1);

    float cell = state[c];
    const float wz  = wvz[h];
    const float wfh = 0.5f * wvf[h];

    const float* zp = g_z + c;
    const float* fp = g_f + c;
    float*       op = out + c;

    float zb[4][8], fb[4][8];
#pragma unroll
    for (int j = 0; j < 2; j++)
#pragma unroll
        for (int i = 0; i < 8; i++) {
            size_t off = (size_t)(j * 8 + i) * M_TOTAL;
            zb[j][i] = zp[off];
            fb[j][i] = fp[off];
        }

#pragma unroll 1
    for (int ob = 0; ob < 32; ++ob) {
#pragma unroll
        for (int j = 0; j < 4; ++j) {
            const int blk = ob * 4 + j;
            const int nb  = blk + 2;
            const int nbuf = (j + 2) & 3;
            if (nb < 128) {
#pragma unroll
                for (int i = 0; i < 8; i++) {
                    size_t off = (size_t)(nb * 8 + i) * M_TOTAL;
                    zb[nbuf][i] = zp[off];
                    fb[nbuf][i] = fp[off];
                }
            }
#pragma unroll
            for (int i = 0; i < 8; i++) {
                float zpart = tanh_fast(fmaf(wz,  cell, zb[j][i]));
                float t     = tanh_fast(fmaf(wfh, cell, fb[j][i]));
                float fpart = fmaf(0.5f, t, 0.5f);
                cell = fmaf(fpart, cell - zpart, zpart);
                op[(size_t)(blk * 8 + i) * M_TOTAL] = cell;
            }
        }
    }
}

// ============ launch ============
extern "C" void kernel_launch(void* const* d_in, const int* in_sizes, int n_in,
                              void* d_out, int out_size) {
    const float* x      = (const float*)d_in[0];
    const float* state  = (const float*)d_in[1];
    const float* wm_z   = (const float*)d_in[2];
    const float* wm_f   = (const float*)d_in[3];
    const float* wv_z   = (const float*)d_in[4];
    const float* wv_f   = (const float*)d_in[5];
    const float* bias_z = (const float*)d_in[6];
    const float* bias_f = (const float*)d_in[7];
    float* out = (float*)d_out;

    float *af, *bf;
    cudaGetSymbolAddress((void**)&af, g_af);
    cudaGetSymbolAddress((void**)&bf, g_bf);

    cudaFuncSetAttribute(gemm_tc, cudaFuncAttributeMaxDynamicSharedMemorySize, SMEM_BYTES);

    // A units: (M/16)*(K/8)*32 lanes = 8,388,608 threads -> 32768 blocks of 256
    prep_a<<<32768, 256>>>(x, af);
    // B units: (Nf/8)*(K/8)*32 lanes = 1,048,576 threads -> 4096 blocks of 256
    prep_b<<<4096, 256>>>(wm_z, wm_f, bf);

    dim3 grid(NFUSED / BN, M_TOTAL / BM);   // (8, 256)
    gemm_tc<<<grid, 256, SMEM_BYTES>>>(af, bf, bias_z, bias_f);

    scan_kernel<<<M_TOTAL / 128, 128>>>(state, wv_z, wv_f, out);
}